// round 8
// baseline (speedup 1.0000x reference)
#include <cuda_runtime.h>
#include <cstdint>

#define BB      8
#define CTOT    256
#define HH      96
#define WW      128
#define ROWT    HH                 // one output row per block
#define CCK     2                  // channels per chunk
#define NCHUNK  (CTOT/CCK)         // 128
#define NBUF    6                  // ring of 6 buffers
#define DEPTH   5                  // prefetch distance (chunks)
#define THREADS 288                // 9 warps, one dy each
#define CHS     (HH*WW)            // channel stride (floats)

#define ROWB       576                         // bytes per halo row (136 used, padded)
#define WARP_SEG   (CCK*ROWB)                  // 1152 B per warp per buffer
#define BUF_BYTES  (9*WARP_SEG)                // 10368
#define SMEM_TOTAL (NBUF*BUF_BYTES)            // 62208 -> 3 blocks/SM

typedef unsigned long long ull;

__device__ __forceinline__ float4 lds128(uint32_t addr) {
    float4 v;
    asm volatile("ld.shared.v4.f32 {%0,%1,%2,%3}, [%4];"
                 : "=f"(v.x), "=f"(v.y), "=f"(v.z), "=f"(v.w) : "r"(addr));
    return v;
}
__device__ __forceinline__ void sts_zero16(uint32_t addr) {
    asm volatile("st.shared.v4.b32 [%0], {%1,%1,%1,%1};" :: "r"(addr), "r"(0) : "memory");
}
__device__ __forceinline__ void cpa16(uint32_t dst, const float* src) {
    asm volatile("cp.async.cg.shared.global [%0], [%1], 16;" :: "r"(dst), "l"(src));
}
__device__ __forceinline__ ull pk(float lo, float hi) {
    ull r;
    asm("mov.b64 %0, {%1,%2};" : "=l"(r) : "f"(lo), "f"(hi));
    return r;
}
__device__ __forceinline__ float2 upk(ull v) {
    float2 f;
    asm("mov.b64 {%0,%1}, %2;" : "=f"(f.x), "=f"(f.y) : "l"(v));
    return f;
}
__device__ __forceinline__ void ffma2(ull& d, ull a, ull b) {
    asm("fma.rn.f32x2 %0, %1, %2, %0;" : "+l"(d) : "l"(a), "l"(b));
}

// Warp-private loader: this warp's halo row, CCK channels, lane = 16B chunk.
// Always commits (keeps per-warp group counting uniform even when row is OOB).
__device__ __forceinline__ void load_chunk(uint32_t wbuf, const float* srcRow,
                                           int lane, bool rowOK)
{
    if (rowOK) {
        const uint32_t dst0 = wbuf + (uint32_t)(16 + lane * 16);
        const float* s = srcRow + lane * 4;
#pragma unroll
        for (int c = 0; c < CCK; c++)
            cpa16(dst0 + c * ROWB, s + (size_t)c * CHS);
    }
    asm volatile("cp.async.commit_group;" ::: "memory");
}

__device__ __forceinline__ void compute_chunk(uint32_t wbuf, const float* pA,
                                              uint32_t offB, ull acc[9][2])
{
#pragma unroll
    for (int cc = 0; cc < CCK; cc++) {
        float4 qa = __ldg((const float4*)(pA + (size_t)cc * CHS));
        const uint32_t rb = wbuf + cc * ROWB + offB;
        float4 q0 = lds128(rb);
        float4 q1 = lds128(rb + 16);
        float4 q2 = lds128(rb + 32);

        ull A0 = pk(qa.x, qa.y);
        ull A1 = pk(qa.z, qa.w);

        float f[12] = { q0.x, q0.y, q0.z, q0.w,
                        q1.x, q1.y, q1.z, q1.w,
                        q2.x, q2.y, q2.z, q2.w };
        ull E[6], O[5];
#pragma unroll
        for (int j = 0; j < 6; j++) E[j] = pk(f[2 * j], f[2 * j + 1]);
#pragma unroll
        for (int j = 0; j < 5; j++) O[j] = pk(f[2 * j + 1], f[2 * j + 2]);

#pragma unroll
        for (int d = 0; d < 9; d++) {
            ull b0 = (d & 1) ? O[(d >> 1)]     : E[(d >> 1)];
            ull b1 = (d & 1) ? O[(d >> 1) + 1] : E[(d >> 1) + 1];
            ffma2(acc[d][0], A0, b0);
            ffma2(acc[d][1], A1, b1);
        }
    }
}

__global__ void __launch_bounds__(THREADS, 3)
corr_kernel(const float* __restrict__ in1, const float* __restrict__ in2,
            float* __restrict__ out)
{
    extern __shared__ char smem[];
    const uint32_t smem32 = (uint32_t)__cvta_generic_to_shared(smem);

    const int tid  = threadIdx.x;
    const int warp = tid >> 5;         // dy 0..8
    const int lane = tid & 31;
    const int x0   = lane << 2;        // 4 px per lane

    const int bx = blockIdx.x;
    const int b  = bx / ROWT;
    const int h0 = bx - b * ROWT;      // output row

    const int hB = h0 + warp - 4;      // this warp's in2 source row
    const bool rowOK = (hB >= 0) && (hB < HH);

    // Rotating warp-private ring buffer addresses
    const uint32_t wbBase = smem32 + (uint32_t)(warp * WARP_SEG);
    const uint32_t wbEnd  = wbBase + SMEM_TOTAL;
    // B window for lane: floats [x0-4 .. x0+11] -> byte 16*lane within a row
    const uint32_t offB = (uint32_t)(16 * lane);

    // Lane-local pre-zero of all ring rows (reader == writer; no sync needed).
#pragma unroll
    for (int buf = 0; buf < NBUF; buf++) {
#pragma unroll
        for (int cc = 0; cc < CCK; cc++) {
            const uint32_t rb = wbBase + buf * BUF_BYTES + cc * ROWB;
            if (!rowOK) {
                sts_zero16(rb + offB);
                sts_zero16(rb + offB + 16);
                sts_zero16(rb + offB + 32);
            } else {
                if (lane == 0)  sts_zero16(rb);          // left pad (floats -4..-1)
                if (lane == 31) sts_zero16(rb + 528);    // right pad (floats 128..131)
            }
        }
    }

    const float* pAc = in1 + (size_t)(b * CTOT) * CHS + h0 * WW + x0;
    const float* sp  = in2 + (size_t)(b * CTOT) * CHS + (rowOK ? hB : 0) * WW;
    const size_t CSTEP = (size_t)CCK * CHS;

    ull acc[9][2];
#pragma unroll
    for (int d = 0; d < 9; d++) { acc[d][0] = 0ull; acc[d][1] = 0ull; }

    // Prologue: fill DEPTH buffers (DEPTH groups pending)
    uint32_t wbNxt = wbBase;
#pragma unroll
    for (int i = 0; i < DEPTH; i++) {
        load_chunk(wbNxt, sp, lane, rowOK);
        sp += CSTEP;
        wbNxt += BUF_BYTES;
    }
    uint32_t wbCur = wbBase;

    for (int k = 0; k < NCHUNK; k++) {
        if (k + DEPTH < NCHUNK) {
            load_chunk(wbNxt, sp, lane, rowOK);
            sp += CSTEP;
            wbNxt += BUF_BYTES;
            if (wbNxt >= wbEnd) wbNxt -= SMEM_TOTAL;
            asm volatile("cp.async.wait_group 5;" ::: "memory");
        } else if (k + 4 < NCHUNK) {
            asm volatile("cp.async.wait_group 4;" ::: "memory");
        } else if (k + 3 < NCHUNK) {
            asm volatile("cp.async.wait_group 3;" ::: "memory");
        } else if (k + 2 < NCHUNK) {
            asm volatile("cp.async.wait_group 2;" ::: "memory");
        } else if (k + 1 < NCHUNK) {
            asm volatile("cp.async.wait_group 1;" ::: "memory");
        } else {
            asm volatile("cp.async.wait_group 0;" ::: "memory");
        }
        compute_chunk(wbCur, pAc, offB, acc);
        pAc += CSTEP;
        wbCur += BUF_BYTES;
        if (wbCur >= wbEnd) wbCur -= SMEM_TOTAL;
    }

    // Epilogue: out[b, warp*9+d, h0, x0..x0+3] = acc / 256
    const float inv = 1.0f / 256.0f;
#pragma unroll
    for (int d = 0; d < 9; d++) {
        const int n = warp * 9 + d;
        float* op = out + ((size_t)((b * 81 + n) * HH + h0)) * WW + x0;
        float2 u0 = upk(acc[d][0]);
        float2 u1 = upk(acc[d][1]);
        *(float4*)op = make_float4(u0.x * inv, u0.y * inv, u1.x * inv, u1.y * inv);
    }
}

extern "C" void kernel_launch(void* const* d_in, const int* in_sizes, int n_in,
                              void* d_out, int out_size)
{
    const float* in1 = (const float*)d_in[0];
    const float* in2 = (const float*)d_in[1];
    float* out = (float*)d_out;

    cudaFuncSetAttribute(corr_kernel, cudaFuncAttributeMaxDynamicSharedMemorySize, SMEM_TOTAL);
    corr_kernel<<<BB * ROWT, THREADS, SMEM_TOTAL>>>(in1, in2, out);
}